// round 1
// baseline (speedup 1.0000x reference)
#include <cuda_runtime.h>
#include <cuda_bf16.h>
#include <math.h>

#define B_   2
#define S_   2048
#define D_   2048
#define H_   16
#define KVH_ 8
#define HD_  128
#define M_   (B_ * S_)          // 4096
#define NQ_  (H_ * HD_)         // 2048
#define NKV_ (KVH_ * HD_)       // 1024
#define REP_ (H_ / KVH_)        // 2
#define EPS_ 1e-6f

// ---------------- scratch (device globals, allocation-free) ----------------
__device__ float g_qproj[M_ * NQ_];   // 32 MB
__device__ float g_kproj[M_ * NKV_];  // 16 MB
__device__ float g_vproj[M_ * NKV_];  // 16 MB
__device__ float g_Q[M_ * NQ_];       // [B,H,S,HD]
__device__ float g_K[M_ * NKV_];      // [B,KVH,S,HD]
__device__ float g_V[M_ * NKV_];      // [B,KVH,S,HD]
__device__ float g_att[M_ * NQ_];     // [m, H*HD]

// ---------------- dequant GEMM: C[m,n] = s[n] * dot(A[m,:], W[n,:]) --------
// A: [M,K] f32 row-major; W: [N,K] int32 row-major; scale: [N]
#define BM 128
#define BN 128
#define BK 16
#define TM 8
#define TN 8

__global__ __launch_bounds__(256, 2)
void gemm_deq(const float* __restrict__ A, const int* __restrict__ W,
              const float* __restrict__ scale, float* __restrict__ C,
              int M, int N, int K) {
    __shared__ float As[BK][BM];
    __shared__ float Bs[BK][BN];

    const int bm = blockIdx.y * BM;
    const int bn = blockIdx.x * BN;
    const int tid = threadIdx.x;
    const int tr = tid / 16;
    const int tc = tid % 16;

    float acc[TM][TN] = {};

    for (int k0 = 0; k0 < K; k0 += BK) {
        // load A tile (128 x 16), transposed into As[k][m]
        #pragma unroll
        for (int i = 0; i < 2; i++) {
            int slot = tid + i * 256;          // 0..511
            int row = slot >> 2;               // 0..127
            int kc = (slot & 3) << 2;          // 0,4,8,12
            float4 v = *(const float4*)&A[(size_t)(bm + row) * K + k0 + kc];
            As[kc + 0][row] = v.x; As[kc + 1][row] = v.y;
            As[kc + 2][row] = v.z; As[kc + 3][row] = v.w;
        }
        // load W tile (128 x 16), int -> float, into Bs[k][n]
        #pragma unroll
        for (int i = 0; i < 2; i++) {
            int slot = tid + i * 256;
            int row = slot >> 2;
            int kc = (slot & 3) << 2;
            int4 w = *(const int4*)&W[(size_t)(bn + row) * K + k0 + kc];
            Bs[kc + 0][row] = (float)w.x; Bs[kc + 1][row] = (float)w.y;
            Bs[kc + 2][row] = (float)w.z; Bs[kc + 3][row] = (float)w.w;
        }
        __syncthreads();

        #pragma unroll
        for (int k = 0; k < BK; k++) {
            float ar[TM], br[TN];
            float4 a0 = *(float4*)&As[k][tr * TM];
            float4 a1 = *(float4*)&As[k][tr * TM + 4];
            ar[0]=a0.x; ar[1]=a0.y; ar[2]=a0.z; ar[3]=a0.w;
            ar[4]=a1.x; ar[5]=a1.y; ar[6]=a1.z; ar[7]=a1.w;
            float4 b0 = *(float4*)&Bs[k][tc * TN];
            float4 b1 = *(float4*)&Bs[k][tc * TN + 4];
            br[0]=b0.x; br[1]=b0.y; br[2]=b0.z; br[3]=b0.w;
            br[4]=b1.x; br[5]=b1.y; br[6]=b1.z; br[7]=b1.w;
            #pragma unroll
            for (int i = 0; i < TM; i++)
                #pragma unroll
                for (int j = 0; j < TN; j++)
                    acc[i][j] = fmaf(ar[i], br[j], acc[i][j]);
        }
        __syncthreads();
    }

    #pragma unroll
    for (int i = 0; i < TM; i++) {
        size_t m = bm + tr * TM + i;
        #pragma unroll
        for (int j = 0; j < TN; j++) {
            int n = bn + tc * TN + j;
            C[m * N + n] = acc[i][j] * scale[n];
        }
    }
}

// ---------------- fused RMSNorm + RoPE + head transpose ----------------
// grid.x = M (4096), grid.y = 32 roles: [0,16) q heads, [16,24) k heads, [24,32) v heads
// block = 128 threads (one per HD element)
__global__ void norm_rope(const float* __restrict__ qnw, const float* __restrict__ knw,
                          const float* __restrict__ cosc, const float* __restrict__ sinc) {
    const int m = blockIdx.x;
    const int role = blockIdx.y;
    const int d = threadIdx.x;
    const int b = m / S_;
    const int s = m % S_;

    if (role >= 24) {                 // V: pure transpose
        int h = role - 24;
        g_V[((size_t)(b * KVH_ + h) * S_ + s) * HD_ + d] =
            g_vproj[(size_t)m * NKV_ + h * HD_ + d];
        return;
    }

    const float* src;
    const float* nw;
    float* dst;
    int h;
    if (role < 16) {                  // Q
        h = role;
        src = &g_qproj[(size_t)m * NQ_ + h * HD_];
        nw = qnw;
        dst = &g_Q[((size_t)(b * H_ + h) * S_ + s) * HD_];
    } else {                          // K
        h = role - 16;
        src = &g_kproj[(size_t)m * NKV_ + h * HD_];
        nw = knw;
        dst = &g_K[((size_t)(b * KVH_ + h) * S_ + s) * HD_];
    }

    float val = src[d];
    float ss = val * val;
    #pragma unroll
    for (int o = 16; o > 0; o >>= 1) ss += __shfl_xor_sync(0xffffffffu, ss, o);
    __shared__ float wred[4];
    if ((d & 31) == 0) wred[d >> 5] = ss;
    __syncthreads();
    float tot = wred[0] + wred[1] + wred[2] + wred[3];
    float rms = rsqrtf(tot * (1.0f / HD_) + EPS_);

    int dp = (d < 64) ? d + 64 : d - 64;
    float sgn = (d < 64) ? -1.0f : 1.0f;
    float xn = val * rms * nw[d];
    float xp = src[dp] * rms * nw[dp];
    float c = cosc[(size_t)s * HD_ + d];
    float sn = sinc[(size_t)s * HD_ + d];
    dst[d] = xn * c + sgn * xp * sn;
}

// ---------------- flash attention (fp32, causal, GQA) ----------------
#define BQ 64
#define BKV 64
#define ATT_SMEM ((3 * BQ * HD_ + BQ * BKV + 3 * BQ) * sizeof(float))

__global__ __launch_bounds__(256, 1)
void attn_kernel() {
    extern __shared__ float sm[];
    float* Qs = sm;                       // 64*128
    float* Ks = Qs + BQ * HD_;            // 64*128
    float* Vs = Ks + BKV * HD_;           // 64*128
    float* Ps = Vs + BKV * HD_;           // 64*64
    float* rowm = Ps + BQ * BKV;
    float* rowl = rowm + BQ;
    float* rowscale = rowl + BQ;

    const int qt = blockIdx.x;            // q tile 0..31
    const int bh = blockIdx.y;            // 0..31
    const int b = bh / H_;
    const int h = bh % H_;
    const int kvh = h / REP_;
    const int q0 = qt * BQ;

    const float* Qg = g_Q + ((size_t)(b * H_ + h) * S_ + q0) * HD_;
    const float* Kg = g_K + (size_t)(b * KVH_ + kvh) * S_ * HD_;
    const float* Vg = g_V + (size_t)(b * KVH_ + kvh) * S_ * HD_;

    const int tid = threadIdx.x;
    const int tr = tid / 16;              // 0..15
    const int tc = tid % 16;              // 0..15

    // load Q tile: 64*128 floats = 2048 float4, 256 threads -> 8 each
    #pragma unroll
    for (int i = 0; i < 8; i++) {
        int idx = tid + i * 256;          // float4 index
        ((float4*)Qs)[idx] = ((const float4*)Qg)[idx];
    }
    if (tid < BQ) { rowm[tid] = -INFINITY; rowl[tid] = 0.0f; }

    float o_acc[4][8] = {};
    const float sc = rsqrtf((float)HD_);

    for (int kt = 0; kt <= qt; kt++) {
        const int k0 = kt * BKV;
        __syncthreads();   // prev PV done before overwriting Ks/Vs (also covers Q load)
        #pragma unroll
        for (int i = 0; i < 8; i++) {
            int idx = tid + i * 256;
            ((float4*)Ks)[idx] = ((const float4*)(Kg + (size_t)k0 * HD_))[idx];
            ((float4*)Vs)[idx] = ((const float4*)(Vg + (size_t)k0 * HD_))[idx];
        }
        __syncthreads();

        // S = Q K^T * scale
        float s4[4][4] = {};
        #pragma unroll 4
        for (int d0 = 0; d0 < HD_; d0 += 4) {
            float4 qv[4], kv[4];
            #pragma unroll
            for (int i = 0; i < 4; i++) qv[i] = *(float4*)&Qs[(tr * 4 + i) * HD_ + d0];
            #pragma unroll
            for (int j = 0; j < 4; j++) kv[j] = *(float4*)&Ks[(tc * 4 + j) * HD_ + d0];
            #pragma unroll
            for (int i = 0; i < 4; i++)
                #pragma unroll
                for (int j = 0; j < 4; j++) {
                    s4[i][j] = fmaf(qv[i].x, kv[j].x, s4[i][j]);
                    s4[i][j] = fmaf(qv[i].y, kv[j].y, s4[i][j]);
                    s4[i][j] = fmaf(qv[i].z, kv[j].z, s4[i][j]);
                    s4[i][j] = fmaf(qv[i].w, kv[j].w, s4[i][j]);
                }
        }
        // scale + causal mask
        #pragma unroll
        for (int i = 0; i < 4; i++)
            #pragma unroll
            for (int j = 0; j < 4; j++) {
                s4[i][j] *= sc;
                if (k0 + tc * 4 + j > q0 + tr * 4 + i) s4[i][j] = -INFINITY;
            }

        // online softmax (per-row reduction over 16 tc threads)
        float oldm[4], newm[4], rs[4];
        #pragma unroll
        for (int i = 0; i < 4; i++) {
            int r = tr * 4 + i;
            oldm[i] = rowm[r];
            float mx = fmaxf(fmaxf(s4[i][0], s4[i][1]), fmaxf(s4[i][2], s4[i][3]));
            #pragma unroll
            for (int o = 8; o > 0; o >>= 1)
                mx = fmaxf(mx, __shfl_xor_sync(0xffffffffu, mx, o));
            newm[i] = fmaxf(oldm[i], mx);
            float rsum = 0.0f;
            #pragma unroll
            for (int j = 0; j < 4; j++) {
                float p = (s4[i][j] == -INFINITY) ? 0.0f : __expf(s4[i][j] - newm[i]);
                s4[i][j] = p;
                rsum += p;
            }
            #pragma unroll
            for (int o = 8; o > 0; o >>= 1)
                rsum += __shfl_xor_sync(0xffffffffu, rsum, o);
            rs[i] = rsum;
        }
        if (tc == 0) {
            #pragma unroll
            for (int i = 0; i < 4; i++) {
                int r = tr * 4 + i;
                float scale_o = __expf(oldm[i] - newm[i]);  // exp(-inf)=0 first iter
                rowscale[r] = scale_o;
                rowm[r] = newm[i];
                rowl[r] = rowl[r] * scale_o + rs[i];
            }
        }
        // store P
        #pragma unroll
        for (int i = 0; i < 4; i++)
            #pragma unroll
            for (int j = 0; j < 4; j++)
                Ps[(tr * 4 + i) * BKV + tc * 4 + j] = s4[i][j];
        __syncthreads();

        // O rescale + O += P @ V
        #pragma unroll
        for (int i = 0; i < 4; i++) {
            float so = rowscale[tr * 4 + i];
            #pragma unroll
            for (int j = 0; j < 8; j++) o_acc[i][j] *= so;
        }
        #pragma unroll 4
        for (int c = 0; c < BKV; c++) {
            float pr[4];
            #pragma unroll
            for (int i = 0; i < 4; i++) pr[i] = Ps[(tr * 4 + i) * BKV + c];
            float4 v0 = *(float4*)&Vs[c * HD_ + tc * 8];
            float4 v1 = *(float4*)&Vs[c * HD_ + tc * 8 + 4];
            #pragma unroll
            for (int i = 0; i < 4; i++) {
                o_acc[i][0] = fmaf(pr[i], v0.x, o_acc[i][0]);
                o_acc[i][1] = fmaf(pr[i], v0.y, o_acc[i][1]);
                o_acc[i][2] = fmaf(pr[i], v0.z, o_acc[i][2]);
                o_acc[i][3] = fmaf(pr[i], v0.w, o_acc[i][3]);
                o_acc[i][4] = fmaf(pr[i], v1.x, o_acc[i][4]);
                o_acc[i][5] = fmaf(pr[i], v1.y, o_acc[i][5]);
                o_acc[i][6] = fmaf(pr[i], v1.z, o_acc[i][6]);
                o_acc[i][7] = fmaf(pr[i], v1.w, o_acc[i][7]);
            }
        }
    }
    __syncthreads();

    // epilogue: divide by l, write to g_att [m, H*HD]
    #pragma unroll
    for (int i = 0; i < 4; i++) {
        int r = tr * 4 + i;
        float inv = 1.0f / rowl[r];
        size_t off = ((size_t)(b * S_) + q0 + r) * NQ_ + h * HD_ + tc * 8;
        float4 w0, w1;
        w0.x = o_acc[i][0] * inv; w0.y = o_acc[i][1] * inv;
        w0.z = o_acc[i][2] * inv; w0.w = o_acc[i][3] * inv;
        w1.x = o_acc[i][4] * inv; w1.y = o_acc[i][5] * inv;
        w1.z = o_acc[i][6] * inv; w1.w = o_acc[i][7] * inv;
        *(float4*)&g_att[off] = w0;
        *(float4*)&g_att[off + 4] = w1;
    }
}

// ---------------- launch ----------------
extern "C" void kernel_launch(void* const* d_in, const int* in_sizes, int n_in,
                              void* d_out, int out_size) {
    const float* x    = (const float*)d_in[0];
    const int*   wq   = (const int*)  d_in[1];
    const float* wqs  = (const float*)d_in[2];
    const int*   wk   = (const int*)  d_in[3];
    const float* wks  = (const float*)d_in[4];
    const int*   wv   = (const int*)  d_in[5];
    const float* wvs  = (const float*)d_in[6];
    const int*   wo   = (const int*)  d_in[7];
    const float* wos  = (const float*)d_in[8];
    const float* qnw  = (const float*)d_in[9];
    const float* knw  = (const float*)d_in[10];
    const float* cosc = (const float*)d_in[11];
    const float* sinc = (const float*)d_in[12];
    float* out = (float*)d_out;

    float *qp, *kp, *vp, *att;
    cudaGetSymbolAddress((void**)&qp,  g_qproj);
    cudaGetSymbolAddress((void**)&kp,  g_kproj);
    cudaGetSymbolAddress((void**)&vp,  g_vproj);
    cudaGetSymbolAddress((void**)&att, g_att);

    // QKV dequant projections
    gemm_deq<<<dim3(NQ_ / BN,  M_ / BM), 256>>>(x, wq, wqs, qp, M_, NQ_,  D_);
    gemm_deq<<<dim3(NKV_ / BN, M_ / BM), 256>>>(x, wk, wks, kp, M_, NKV_, D_);
    gemm_deq<<<dim3(NKV_ / BN, M_ / BM), 256>>>(x, wv, wvs, vp, M_, NKV_, D_);

    // RMSNorm + RoPE + transpose
    norm_rope<<<dim3(M_, H_ + 2 * KVH_), 128>>>(qnw, knw, cosc, sinc);

    // flash attention
    cudaFuncSetAttribute(attn_kernel, cudaFuncAttributeMaxDynamicSharedMemorySize,
                         (int)ATT_SMEM);
    attn_kernel<<<dim3(S_ / BQ, B_ * H_), 256, ATT_SMEM>>>();

    // output projection
    gemm_deq<<<dim3(NQ_ / BN, M_ / BM), 256>>>(att, wo, wos, out, M_, NQ_, D_);
}

// round 3
// speedup vs baseline: 1.5602x; 1.5602x over previous
#include <cuda_runtime.h>
#include <cuda_bf16.h>
#include <math.h>
#include <stdint.h>

#define B_   2
#define S_   2048
#define D_   2048
#define H_   16
#define KVH_ 8
#define HD_  128
#define M_   (B_ * S_)          // 4096
#define NQ_  (H_ * HD_)         // 2048
#define NKV_ (KVH_ * HD_)       // 1024
#define REP_ (H_ / KVH_)        // 2
#define EPS_ 1e-6f

// ---------------- scratch (device globals, allocation-free) ----------------
__device__ __align__(256) float g_qproj[M_ * NQ_];
__device__ __align__(256) float g_kproj[M_ * NKV_];
__device__ __align__(256) float g_vproj[M_ * NKV_];
__device__ __align__(256) float g_Q[M_ * NQ_];
__device__ __align__(256) float g_K[M_ * NKV_];
__device__ __align__(256) float g_V[M_ * NKV_];
__device__ __align__(256) __nv_bfloat16 g_xhi[M_ * D_];
__device__ __align__(256) __nv_bfloat16 g_xlo[M_ * D_];
__device__ __align__(256) __nv_bfloat16 g_ahi[M_ * NQ_];
__device__ __align__(256) __nv_bfloat16 g_alo[M_ * NQ_];
__device__ __align__(256) __nv_bfloat16 g_wqb[NQ_ * D_];
__device__ __align__(256) __nv_bfloat16 g_wkb[NKV_ * D_];
__device__ __align__(256) __nv_bfloat16 g_wvb[NKV_ * D_];
__device__ __align__(256) __nv_bfloat16 g_wob[D_ * NQ_];

// ---------------- PTX helpers (baseline PTX only, no arch-suffix features) --
__device__ __forceinline__ uint32_t smem_u32(const void* p) {
    uint32_t a;
    asm("{ .reg .u64 t; cvta.to.shared.u64 t, %1; cvt.u32.u64 %0, t; }" : "=r"(a) : "l"(p));
    return a;
}
__device__ __forceinline__ void cp16(uint32_t s, const void* g) {
    asm volatile("cp.async.cg.shared.global [%0], [%1], 16;" :: "r"(s), "l"(g));
}
#define CP_COMMIT() asm volatile("cp.async.commit_group;" ::: "memory")
#define CP_WAIT(n)  asm volatile("cp.async.wait_group %0;" :: "n"(n) : "memory")

__device__ __forceinline__ void ldm4(uint32_t* r, uint32_t addr) {
    asm volatile("ldmatrix.sync.aligned.m8n8.x4.shared.b16 {%0,%1,%2,%3}, [%4];"
                 : "=r"(r[0]), "=r"(r[1]), "=r"(r[2]), "=r"(r[3]) : "r"(addr));
}
__device__ __forceinline__ void mma16816(float* c, const uint32_t* a, const uint32_t* b) {
    asm volatile("mma.sync.aligned.m16n8k16.row.col.f32.bf16.bf16.f32 "
                 "{%0,%1,%2,%3}, {%4,%5,%6,%7}, {%8,%9}, {%0,%1,%2,%3};"
                 : "+f"(c[0]), "+f"(c[1]), "+f"(c[2]), "+f"(c[3])
                 : "r"(a[0]), "r"(a[1]), "r"(a[2]), "r"(a[3]), "r"(b[0]), "r"(b[1]));
}

// SW128 swizzle: XOR bits[4:6] with bits[7:9] -> conflict-free ldmatrix on 128B rows
__device__ __forceinline__ uint32_t sw128(uint32_t off) { return off ^ ((off >> 3) & 0x70); }

// ---------------- conversion kernels ----------------
__global__ void split_x_kernel(const float* __restrict__ x,
                               __nv_bfloat16* __restrict__ hi,
                               __nv_bfloat16* __restrict__ lo) {
    int i = blockIdx.x * blockDim.x + threadIdx.x;  // one float4
    float4 v = ((const float4*)x)[i];
    __nv_bfloat16 h[4], l[4];
    float vv[4] = {v.x, v.y, v.z, v.w};
    #pragma unroll
    for (int j = 0; j < 4; j++) {
        h[j] = __float2bfloat16(vv[j]);
        l[j] = __float2bfloat16(vv[j] - __bfloat162float(h[j]));
    }
    ((uint2*)hi)[i] = *(uint2*)h;
    ((uint2*)lo)[i] = *(uint2*)l;
}

__global__ void cvt_w_kernel(const int* __restrict__ w, __nv_bfloat16* __restrict__ o) {
    int i = blockIdx.x * blockDim.x + threadIdx.x;  // one int4
    int4 v = ((const int4*)w)[i];
    __nv_bfloat16 b[4];
    b[0] = __float2bfloat16((float)v.x);
    b[1] = __float2bfloat16((float)v.y);
    b[2] = __float2bfloat16((float)v.z);
    b[3] = __float2bfloat16((float)v.w);
    ((uint2*)o)[i] = *(uint2*)b;
}

// ---------------- mma.sync bf16 GEMM with hi/lo split ----------------
// C[m,n] = scale[n] * sum_k (Ahi[m,k]+Alo[m,k]) * W[n,k]
// A tiles hi/lo [128][64] bf16 SW128; W tile [128][64] bf16 SW128; 3-stage cp.async.
#define GBK       64
#define GCHUNK    (D_ / GBK)          // 32
#define GTILE_B   16384               // 128 rows x 128B
#define GSTAGE_B  (3 * GTILE_B)       // Ahi, Alo, W
#define GSTG      3
#define GSMEM_DYN (GSTG * GSTAGE_B + 1024)

__device__ __forceinline__ void g_load_chunk(
    uint32_t tbase, int buf, int kc,
    const __nv_bfloat16* __restrict__ Ahi, const __nv_bfloat16* __restrict__ Alo,
    const __nv_bfloat16* __restrict__ W, int bm, int bn, int tid) {
    uint32_t st = tbase + buf * GSTAGE_B;
    const __nv_bfloat16* Ah = Ahi + (size_t)bm * D_ + kc * GBK;
    const __nv_bfloat16* Al = Alo + (size_t)bm * D_ + kc * GBK;
    const __nv_bfloat16* Wp = W   + (size_t)bn * D_ + kc * GBK;
    #pragma unroll
    for (int t = 0; t < 4; t++) {
        int idx = tid + t * 256;            // 0..1023
        int row = idx >> 3;                 // 0..127
        int seg = idx & 7;                  // 16B segment within 128B row
        uint32_t off = sw128((uint32_t)(row * 128 + seg * 16));
        size_t gofs = (size_t)row * D_ + seg * 8;
        cp16(st + off,                 Ah + gofs);
        cp16(st + GTILE_B + off,       Al + gofs);
        cp16(st + 2 * GTILE_B + off,   Wp + gofs);
    }
    CP_COMMIT();
}

__global__ __launch_bounds__(256, 1)
void gemm_mma(const __nv_bfloat16* __restrict__ Ahi, const __nv_bfloat16* __restrict__ Alo,
              const __nv_bfloat16* __restrict__ W, const float* __restrict__ scale,
              float* __restrict__ C, int N) {
    extern __shared__ char dyns[];
    uint32_t tbase = (smem_u32(dyns) + 1023) & ~1023u;

    const int tid = threadIdx.x;
    const int wid = tid >> 5;
    const int L = tid & 31;
    const int bm = blockIdx.y * 128;
    const int bn = blockIdx.x * 128;
    const int wm = (wid & 3) * 32;          // warp m offset in tile
    const int wn = (wid >> 2) * 64;         // warp n offset in tile

    // prologue: stages 0,1
    g_load_chunk(tbase, 0, 0, Ahi, Alo, W, bm, bn, tid);
    g_load_chunk(tbase, 1, 1, Ahi, Alo, W, bm, bn, tid);

    float acc[2][8][4] = {};                // [mi][n8j][frag]

    // precomputed lane addressing pieces
    const int a_row = (L & 7) + ((L >> 3) & 1) * 8;   // within 16-row A subtile
    const int a_kb  = (L >> 4) * 16;                  // 0 or 16 bytes
    const int b_row = (L & 7) + ((L >> 4) << 3);      // within 16-row B subtile
    const int b_kb  = ((L >> 3) & 1) * 16;

    int buf = 0;
    for (int kc = 0; kc < GCHUNK; kc++) {
        CP_WAIT(1);
        __syncthreads();
        // prefetch chunk kc+2 into the buffer freed last iteration
        if (kc + 2 < GCHUNK) {
            int nb = buf + 2; if (nb >= GSTG) nb -= GSTG;
            g_load_chunk(tbase, nb, kc + 2, Ahi, Alo, W, bm, bn, tid);
        } else {
            CP_COMMIT();
        }

        uint32_t st = tbase + buf * GSTAGE_B;
        #pragma unroll
        for (int ks = 0; ks < 4; ks++) {            // 4 x k16 per chunk
            uint32_t ah[2][4], al[2][4], bb[4][4];
            #pragma unroll
            for (int mi = 0; mi < 2; mi++) {
                uint32_t off = sw128((uint32_t)((wm + mi * 16 + a_row) * 128 + ks * 32 + a_kb));
                ldm4(ah[mi], st + off);
                ldm4(al[mi], st + GTILE_B + off);
            }
            #pragma unroll
            for (int nj = 0; nj < 4; nj++) {
                uint32_t off = sw128((uint32_t)((wn + nj * 16 + b_row) * 128 + ks * 32 + b_kb));
                ldm4(bb[nj], st + 2 * GTILE_B + off);
            }
            #pragma unroll
            for (int mi = 0; mi < 2; mi++)
                #pragma unroll
                for (int j = 0; j < 8; j++) {
                    const uint32_t* bf = &bb[j >> 1][(j & 1) * 2];
                    mma16816(acc[mi][j], ah[mi], bf);
                    mma16816(acc[mi][j], al[mi], bf);
                }
        }
        buf++; if (buf >= GSTG) buf = 0;
    }

    // epilogue: scale + store fp32
    const int g = L >> 2;                    // 0..7
    const int q = L & 3;                     // 0..3
    #pragma unroll
    for (int mi = 0; mi < 2; mi++) {
        #pragma unroll
        for (int j = 0; j < 8; j++) {
            int col = bn + wn + j * 8 + q * 2;
            float s0 = __ldg(&scale[col]);
            float s1 = __ldg(&scale[col + 1]);
            int r0 = bm + wm + mi * 16 + g;
            float2 v0 = make_float2(acc[mi][j][0] * s0, acc[mi][j][1] * s1);
            float2 v1 = make_float2(acc[mi][j][2] * s0, acc[mi][j][3] * s1);
            *(float2*)&C[(size_t)r0 * N + col] = v0;
            *(float2*)&C[(size_t)(r0 + 8) * N + col] = v1;
        }
    }
}

// ---------------- fused RMSNorm + RoPE + head transpose ----------------
__global__ void norm_rope(const float* __restrict__ qnw, const float* __restrict__ knw,
                          const float* __restrict__ cosc, const float* __restrict__ sinc) {
    const int m = blockIdx.x;
    const int role = blockIdx.y;
    const int d = threadIdx.x;
    const int b = m / S_;
    const int s = m % S_;

    if (role >= 24) {                 // V: pure transpose
        int h = role - 24;
        g_V[((size_t)(b * KVH_ + h) * S_ + s) * HD_ + d] =
            g_vproj[(size_t)m * NKV_ + h * HD_ + d];
        return;
    }

    const float* src;
    const float* nw;
    float* dst;
    int h;
    if (role < 16) {                  // Q
        h = role;
        src = &g_qproj[(size_t)m * NQ_ + h * HD_];
        nw = qnw;
        dst = &g_Q[((size_t)(b * H_ + h) * S_ + s) * HD_];
    } else {                          // K
        h = role - 16;
        src = &g_kproj[(size_t)m * NKV_ + h * HD_];
        nw = knw;
        dst = &g_K[((size_t)(b * KVH_ + h) * S_ + s) * HD_];
    }

    float val = src[d];
    float ss = val * val;
    #pragma unroll
    for (int o = 16; o > 0; o >>= 1) ss += __shfl_xor_sync(0xffffffffu, ss, o);
    __shared__ float wred[4];
    if ((d & 31) == 0) wred[d >> 5] = ss;
    __syncthreads();
    float tot = wred[0] + wred[1] + wred[2] + wred[3];
    float rms = rsqrtf(tot * (1.0f / HD_) + EPS_);

    int dp = (d < 64) ? d + 64 : d - 64;
    float sgn = (d < 64) ? -1.0f : 1.0f;
    float xn = val * rms * nw[d];
    float xp = src[dp] * rms * nw[dp];
    float c = cosc[(size_t)s * HD_ + d];
    float sn = sinc[(size_t)s * HD_ + d];
    dst[d] = xn * c + sgn * xp * sn;
}

// ---------------- flash attention (fp32, causal, GQA) ----------------
#define BQ 64
#define BKV 64
#define ATT_SMEM ((3 * BQ * HD_ + BQ * BKV + 3 * BQ) * sizeof(float))

__global__ __launch_bounds__(256, 1)
void attn_kernel() {
    extern __shared__ float sm[];
    float* Qs = sm;
    float* Ks = Qs + BQ * HD_;
    float* Vs = Ks + BKV * HD_;
    float* Ps = Vs + BKV * HD_;
    float* rowm = Ps + BQ * BKV;
    float* rowl = rowm + BQ;
    float* rowscale = rowl + BQ;

    const int qt = blockIdx.x;
    const int bh = blockIdx.y;
    const int b = bh / H_;
    const int h = bh % H_;
    const int kvh = h / REP_;
    const int q0 = qt * BQ;

    const float* Qg = g_Q + ((size_t)(b * H_ + h) * S_ + q0) * HD_;
    const float* Kg = g_K + (size_t)(b * KVH_ + kvh) * S_ * HD_;
    const float* Vg = g_V + (size_t)(b * KVH_ + kvh) * S_ * HD_;

    const int tid = threadIdx.x;
    const int tr = tid / 16;
    const int tc = tid % 16;

    #pragma unroll
    for (int i = 0; i < 8; i++) {
        int idx = tid + i * 256;
        ((float4*)Qs)[idx] = ((const float4*)Qg)[idx];
    }
    if (tid < BQ) { rowm[tid] = -INFINITY; rowl[tid] = 0.0f; }

    float o_acc[4][8] = {};
    const float sc = rsqrtf((float)HD_);

    for (int kt = 0; kt <= qt; kt++) {
        const int k0 = kt * BKV;
        __syncthreads();
        #pragma unroll
        for (int i = 0; i < 8; i++) {
            int idx = tid + i * 256;
            ((float4*)Ks)[idx] = ((const float4*)(Kg + (size_t)k0 * HD_))[idx];
            ((float4*)Vs)[idx] = ((const float4*)(Vg + (size_t)k0 * HD_))[idx];
        }
        __syncthreads();

        float s4[4][4] = {};
        #pragma unroll 4
        for (int d0 = 0; d0 < HD_; d0 += 4) {
            float4 qv[4], kv[4];
            #pragma unroll
            for (int i = 0; i < 4; i++) qv[i] = *(float4*)&Qs[(tr * 4 + i) * HD_ + d0];
            #pragma unroll
            for (int j = 0; j < 4; j++) kv[j] = *(float4*)&Ks[(tc * 4 + j) * HD_ + d0];
            #pragma unroll
            for (int i = 0; i < 4; i++)
                #pragma unroll
                for (int j = 0; j < 4; j++) {
                    s4[i][j] = fmaf(qv[i].x, kv[j].x, s4[i][j]);
                    s4[i][j] = fmaf(qv[i].y, kv[j].y, s4[i][j]);
                    s4[i][j] = fmaf(qv[i].z, kv[j].z, s4[i][j]);
                    s4[i][j] = fmaf(qv[i].w, kv[j].w, s4[i][j]);
                }
        }
        #pragma unroll
        for (int i = 0; i < 4; i++)
            #pragma unroll
            for (int j = 0; j < 4; j++) {
                s4[i][j] *= sc;
                if (k0 + tc * 4 + j > q0 + tr * 4 + i) s4[i][j] = -INFINITY;
            }

        float oldm[4], newm[4], rs[4];
        #pragma unroll
        for (int i = 0; i < 4; i++) {
            int r = tr * 4 + i;
            oldm[i] = rowm[r];
            float mx = fmaxf(fmaxf(s4[i][0], s4[i][1]), fmaxf(s4[i][2], s4[i][3]));
            #pragma unroll
            for (int o = 8; o > 0; o >>= 1)
                mx = fmaxf(mx, __shfl_xor_sync(0xffffffffu, mx, o));
            newm[i] = fmaxf(oldm[i], mx);
            float rsum = 0.0f;
            #pragma unroll
            for (int j = 0; j < 4; j++) {
                float p = (s4[i][j] == -INFINITY) ? 0.0f : __expf(s4[i][j] - newm[i]);
                s4[i][j] = p;
                rsum += p;
            }
            #pragma unroll
            for (int o = 8; o > 0; o >>= 1)
                rsum += __shfl_xor_sync(0xffffffffu, rsum, o);
            rs[i] = rsum;
        }
        if (tc == 0) {
            #pragma unroll
            for (int i = 0; i < 4; i++) {
                int r = tr * 4 + i;
                float scale_o = __expf(oldm[i] - newm[i]);
                rowscale[r] = scale_o;
                rowm[r] = newm[i];
                rowl[r] = rowl[r] * scale_o + rs[i];
            }
        }
        #pragma unroll
        for (int i = 0; i < 4; i++)
            #pragma unroll
            for (int j = 0; j < 4; j++)
                Ps[(tr * 4 + i) * BKV + tc * 4 + j] = s4[i][j];
        __syncthreads();

        #pragma unroll
        for (int i = 0; i < 4; i++) {
            float so = rowscale[tr * 4 + i];
            #pragma unroll
            for (int j = 0; j < 8; j++) o_acc[i][j] *= so;
        }
        #pragma unroll 4
        for (int c = 0; c < BKV; c++) {
            float pr[4];
            #pragma unroll
            for (int i = 0; i < 4; i++) pr[i] = Ps[(tr * 4 + i) * BKV + c];
            float4 v0 = *(float4*)&Vs[c * HD_ + tc * 8];
            float4 v1 = *(float4*)&Vs[c * HD_ + tc * 8 + 4];
            #pragma unroll
            for (int i = 0; i < 4; i++) {
                o_acc[i][0] = fmaf(pr[i], v0.x, o_acc[i][0]);
                o_acc[i][1] = fmaf(pr[i], v0.y, o_acc[i][1]);
                o_acc[i][2] = fmaf(pr[i], v0.z, o_acc[i][2]);
                o_acc[i][3] = fmaf(pr[i], v0.w, o_acc[i][3]);
                o_acc[i][4] = fmaf(pr[i], v1.x, o_acc[i][4]);
                o_acc[i][5] = fmaf(pr[i], v1.y, o_acc[i][5]);
                o_acc[i][6] = fmaf(pr[i], v1.z, o_acc[i][6]);
                o_acc[i][7] = fmaf(pr[i], v1.w, o_acc[i][7]);
            }
        }
    }
    __syncthreads();

    // epilogue: divide by l, write bf16 hi/lo into g_ahi/g_alo [m, H*HD]
    #pragma unroll
    for (int i = 0; i < 4; i++) {
        int r = tr * 4 + i;
        float inv = 1.0f / rowl[r];
        size_t off = ((size_t)(b * S_) + q0 + r) * NQ_ + h * HD_ + tc * 8;
        __nv_bfloat16 hv[8], lv[8];
        #pragma unroll
        for (int j = 0; j < 8; j++) {
            float v = o_acc[i][j] * inv;
            hv[j] = __float2bfloat16(v);
            lv[j] = __float2bfloat16(v - __bfloat162float(hv[j]));
        }
        *(uint4*)&g_ahi[off] = *(uint4*)hv;
        *(uint4*)&g_alo[off] = *(uint4*)lv;
    }
}

// ---------------- launch ----------------
extern "C" void kernel_launch(void* const* d_in, const int* in_sizes, int n_in,
                              void* d_out, int out_size) {
    const float* x    = (const float*)d_in[0];
    const int*   wq   = (const int*)  d_in[1];
    const float* wqs  = (const float*)d_in[2];
    const int*   wk   = (const int*)  d_in[3];
    const float* wks  = (const float*)d_in[4];
    const int*   wv   = (const int*)  d_in[5];
    const float* wvs  = (const float*)d_in[6];
    const int*   wo   = (const int*)  d_in[7];
    const float* wos  = (const float*)d_in[8];
    const float* qnw  = (const float*)d_in[9];
    const float* knw  = (const float*)d_in[10];
    const float* cosc = (const float*)d_in[11];
    const float* sinc = (const float*)d_in[12];
    float* out = (float*)d_out;

    float *qp, *kp, *vp;
    __nv_bfloat16 *xhi, *xlo, *ahi, *alo, *wqb, *wkb, *wvb, *wob;
    cudaGetSymbolAddress((void**)&qp,  g_qproj);
    cudaGetSymbolAddress((void**)&kp,  g_kproj);
    cudaGetSymbolAddress((void**)&vp,  g_vproj);
    cudaGetSymbolAddress((void**)&xhi, g_xhi);
    cudaGetSymbolAddress((void**)&xlo, g_xlo);
    cudaGetSymbolAddress((void**)&ahi, g_ahi);
    cudaGetSymbolAddress((void**)&alo, g_alo);
    cudaGetSymbolAddress((void**)&wqb, g_wqb);
    cudaGetSymbolAddress((void**)&wkb, g_wkb);
    cudaGetSymbolAddress((void**)&wvb, g_wvb);
    cudaGetSymbolAddress((void**)&wob, g_wob);

    // conversions
    split_x_kernel<<<(M_ * D_ / 4) / 256, 256>>>(x, xhi, xlo);
    cvt_w_kernel<<<(NQ_ * D_ / 4) / 256, 256>>>(wq, wqb);
    cvt_w_kernel<<<(NKV_ * D_ / 4) / 256, 256>>>(wk, wkb);
    cvt_w_kernel<<<(NKV_ * D_ / 4) / 256, 256>>>(wv, wvb);
    cvt_w_kernel<<<(NQ_ * D_ / 4) / 256, 256>>>(wo, wob);

    cudaFuncSetAttribute(gemm_mma, cudaFuncAttributeMaxDynamicSharedMemorySize, GSMEM_DYN);

    // QKV dequant projections (tensor core via mma.sync)
    gemm_mma<<<dim3(NQ_ / 128,  M_ / 128), 256, GSMEM_DYN>>>(xhi, xlo, wqb, wqs, qp, NQ_);
    gemm_mma<<<dim3(NKV_ / 128, M_ / 128), 256, GSMEM_DYN>>>(xhi, xlo, wkb, wks, kp, NKV_);
    gemm_mma<<<dim3(NKV_ / 128, M_ / 128), 256, GSMEM_DYN>>>(xhi, xlo, wvb, wvs, vp, NKV_);

    // RMSNorm + RoPE + transpose
    norm_rope<<<dim3(M_, H_ + 2 * KVH_), 128>>>(qnw, knw, cosc, sinc);

    // flash attention (fp32), epilogue emits bf16 hi/lo
    cudaFuncSetAttribute(attn_kernel, cudaFuncAttributeMaxDynamicSharedMemorySize,
                         (int)ATT_SMEM);
    attn_kernel<<<dim3(S_ / BQ, B_ * H_), 256, ATT_SMEM>>>();

    // output projection straight into d_out
    gemm_mma<<<dim3(D_ / 128, M_ / 128), 256, GSMEM_DYN>>>(ahi, alo, wob, wos, out, D_);
}

// round 4
// speedup vs baseline: 6.1545x; 3.9447x over previous
#include <cuda_runtime.h>
#include <cuda_bf16.h>
#include <math.h>
#include <stdint.h>

#define B_   2
#define S_   2048
#define D_   2048
#define H_   16
#define KVH_ 8
#define HD_  128
#define M_   (B_ * S_)          // 4096
#define NQ_  (H_ * HD_)         // 2048
#define NKV_ (KVH_ * HD_)       // 1024
#define REP_ (H_ / KVH_)        // 2
#define EPS_ 1e-6f

// ---------------- scratch (device globals, allocation-free) ----------------
__device__ __align__(256) float g_qproj[M_ * NQ_];
__device__ __align__(256) float g_kproj[M_ * NKV_];
__device__ __align__(256) float g_vproj[M_ * NKV_];
__device__ __align__(256) __nv_bfloat16 g_xhi[M_ * D_];
__device__ __align__(256) __nv_bfloat16 g_xlo[M_ * D_];
__device__ __align__(256) __nv_bfloat16 g_ahi[M_ * NQ_];
__device__ __align__(256) __nv_bfloat16 g_alo[M_ * NQ_];
__device__ __align__(256) __nv_bfloat16 g_wqb[NQ_ * D_];
__device__ __align__(256) __nv_bfloat16 g_wkb[NKV_ * D_];
__device__ __align__(256) __nv_bfloat16 g_wvb[NKV_ * D_];
__device__ __align__(256) __nv_bfloat16 g_wob[D_ * NQ_];
// attention operands, bf16 hi/lo, [B,H(S?),S,HD] layouts
__device__ __align__(256) __nv_bfloat16 g_Qhi[M_ * NQ_];
__device__ __align__(256) __nv_bfloat16 g_Qlo[M_ * NQ_];
__device__ __align__(256) __nv_bfloat16 g_Khi[M_ * NKV_];
__device__ __align__(256) __nv_bfloat16 g_Klo[M_ * NKV_];
__device__ __align__(256) __nv_bfloat16 g_Vhi[M_ * NKV_];
__device__ __align__(256) __nv_bfloat16 g_Vlo[M_ * NKV_];

// ---------------- PTX helpers (baseline PTX only) ----------------
__device__ __forceinline__ uint32_t smem_u32(const void* p) {
    uint32_t a;
    asm("{ .reg .u64 t; cvta.to.shared.u64 t, %1; cvt.u32.u64 %0, t; }" : "=r"(a) : "l"(p));
    return a;
}
__device__ __forceinline__ void cp16(uint32_t s, const void* g) {
    asm volatile("cp.async.cg.shared.global [%0], [%1], 16;" :: "r"(s), "l"(g));
}
#define CP_COMMIT() asm volatile("cp.async.commit_group;" ::: "memory")
#define CP_WAIT(n)  asm volatile("cp.async.wait_group %0;" :: "n"(n) : "memory")

__device__ __forceinline__ void ldm4(uint32_t* r, uint32_t addr) {
    asm volatile("ldmatrix.sync.aligned.m8n8.x4.shared.b16 {%0,%1,%2,%3}, [%4];"
                 : "=r"(r[0]), "=r"(r[1]), "=r"(r[2]), "=r"(r[3]) : "r"(addr));
}
__device__ __forceinline__ void ldm4t(uint32_t* r, uint32_t addr) {
    asm volatile("ldmatrix.sync.aligned.m8n8.x4.trans.shared.b16 {%0,%1,%2,%3}, [%4];"
                 : "=r"(r[0]), "=r"(r[1]), "=r"(r[2]), "=r"(r[3]) : "r"(addr));
}
__device__ __forceinline__ void mma16816(float* c, const uint32_t* a, const uint32_t* b) {
    asm volatile("mma.sync.aligned.m16n8k16.row.col.f32.bf16.bf16.f32 "
                 "{%0,%1,%2,%3}, {%4,%5,%6,%7}, {%8,%9}, {%0,%1,%2,%3};"
                 : "+f"(c[0]), "+f"(c[1]), "+f"(c[2]), "+f"(c[3])
                 : "r"(a[0]), "r"(a[1]), "r"(a[2]), "r"(a[3]), "r"(b[0]), "r"(b[1]));
}

// swizzles: 128B rows and 256B rows
__device__ __forceinline__ uint32_t sw128(uint32_t off) { return off ^ ((off >> 3) & 0x70); }
__device__ __forceinline__ uint32_t sw256(uint32_t off) { return off ^ ((off >> 4) & 0x70); }

// split fp32 pair -> bf16x2 hi + lo
__device__ __forceinline__ void split2(float a, float b, uint32_t& hi, uint32_t& lo) {
    __nv_bfloat162 h = __floats2bfloat162_rn(a, b);
    float ra = a - __bfloat162float(h.x);
    float rb = b - __bfloat162float(h.y);
    __nv_bfloat162 l = __floats2bfloat162_rn(ra, rb);
    hi = *(uint32_t*)&h;
    lo = *(uint32_t*)&l;
}

// ---------------- conversion kernels ----------------
__global__ void split_x_kernel(const float* __restrict__ x,
                               __nv_bfloat16* __restrict__ hi,
                               __nv_bfloat16* __restrict__ lo) {
    int i = blockIdx.x * blockDim.x + threadIdx.x;
    float4 v = ((const float4*)x)[i];
    __nv_bfloat16 h[4], l[4];
    float vv[4] = {v.x, v.y, v.z, v.w};
    #pragma unroll
    for (int j = 0; j < 4; j++) {
        h[j] = __float2bfloat16(vv[j]);
        l[j] = __float2bfloat16(vv[j] - __bfloat162float(h[j]));
    }
    ((uint2*)hi)[i] = *(uint2*)h;
    ((uint2*)lo)[i] = *(uint2*)l;
}

__global__ void cvt_w_kernel(const int* __restrict__ w, __nv_bfloat16* __restrict__ o) {
    int i = blockIdx.x * blockDim.x + threadIdx.x;
    int4 v = ((const int4*)w)[i];
    __nv_bfloat16 b[4];
    b[0] = __float2bfloat16((float)v.x);
    b[1] = __float2bfloat16((float)v.y);
    b[2] = __float2bfloat16((float)v.z);
    b[3] = __float2bfloat16((float)v.w);
    ((uint2*)o)[i] = *(uint2*)b;
}

// ---------------- mma.sync bf16 GEMM with hi/lo split (unchanged, proven) ----
#define GBK       64
#define GCHUNK    (D_ / GBK)
#define GTILE_B   16384
#define GSTAGE_B  (3 * GTILE_B)
#define GSTG      3
#define GSMEM_DYN (GSTG * GSTAGE_B + 1024)

__device__ __forceinline__ void g_load_chunk(
    uint32_t tbase, int buf, int kc,
    const __nv_bfloat16* __restrict__ Ahi, const __nv_bfloat16* __restrict__ Alo,
    const __nv_bfloat16* __restrict__ W, int bm, int bn, int tid) {
    uint32_t st = tbase + buf * GSTAGE_B;
    const __nv_bfloat16* Ah = Ahi + (size_t)bm * D_ + kc * GBK;
    const __nv_bfloat16* Al = Alo + (size_t)bm * D_ + kc * GBK;
    const __nv_bfloat16* Wp = W   + (size_t)bn * D_ + kc * GBK;
    #pragma unroll
    for (int t = 0; t < 4; t++) {
        int idx = tid + t * 256;
        int row = idx >> 3;
        int seg = idx & 7;
        uint32_t off = sw128((uint32_t)(row * 128 + seg * 16));
        size_t gofs = (size_t)row * D_ + seg * 8;
        cp16(st + off,                 Ah + gofs);
        cp16(st + GTILE_B + off,       Al + gofs);
        cp16(st + 2 * GTILE_B + off,   Wp + gofs);
    }
    CP_COMMIT();
}

__global__ __launch_bounds__(256, 1)
void gemm_mma(const __nv_bfloat16* __restrict__ Ahi, const __nv_bfloat16* __restrict__ Alo,
              const __nv_bfloat16* __restrict__ W, const float* __restrict__ scale,
              float* __restrict__ C, int N) {
    extern __shared__ char dyns[];
    uint32_t tbase = (smem_u32(dyns) + 1023) & ~1023u;

    const int tid = threadIdx.x;
    const int wid = tid >> 5;
    const int L = tid & 31;
    const int bm = blockIdx.y * 128;
    const int bn = blockIdx.x * 128;
    const int wm = (wid & 3) * 32;
    const int wn = (wid >> 2) * 64;

    g_load_chunk(tbase, 0, 0, Ahi, Alo, W, bm, bn, tid);
    g_load_chunk(tbase, 1, 1, Ahi, Alo, W, bm, bn, tid);

    float acc[2][8][4] = {};

    const int a_row = (L & 7) + ((L >> 3) & 1) * 8;
    const int a_kb  = (L >> 4) * 16;
    const int b_row = (L & 7) + ((L >> 4) << 3);
    const int b_kb  = ((L >> 3) & 1) * 16;

    int buf = 0;
    for (int kc = 0; kc < GCHUNK; kc++) {
        CP_WAIT(1);
        __syncthreads();
        if (kc + 2 < GCHUNK) {
            int nb = buf + 2; if (nb >= GSTG) nb -= GSTG;
            g_load_chunk(tbase, nb, kc + 2, Ahi, Alo, W, bm, bn, tid);
        } else {
            CP_COMMIT();
        }

        uint32_t st = tbase + buf * GSTAGE_B;
        #pragma unroll
        for (int ks = 0; ks < 4; ks++) {
            uint32_t ah[2][4], al[2][4], bb[4][4];
            #pragma unroll
            for (int mi = 0; mi < 2; mi++) {
                uint32_t off = sw128((uint32_t)((wm + mi * 16 + a_row) * 128 + ks * 32 + a_kb));
                ldm4(ah[mi], st + off);
                ldm4(al[mi], st + GTILE_B + off);
            }
            #pragma unroll
            for (int nj = 0; nj < 4; nj++) {
                uint32_t off = sw128((uint32_t)((wn + nj * 16 + b_row) * 128 + ks * 32 + b_kb));
                ldm4(bb[nj], st + 2 * GTILE_B + off);
            }
            #pragma unroll
            for (int mi = 0; mi < 2; mi++)
                #pragma unroll
                for (int j = 0; j < 8; j++) {
                    const uint32_t* bf = &bb[j >> 1][(j & 1) * 2];
                    mma16816(acc[mi][j], ah[mi], bf);
                    mma16816(acc[mi][j], al[mi], bf);
                }
        }
        buf++; if (buf >= GSTG) buf = 0;
    }

    const int g = L >> 2;
    const int q = L & 3;
    #pragma unroll
    for (int mi = 0; mi < 2; mi++) {
        #pragma unroll
        for (int j = 0; j < 8; j++) {
            int col = bn + wn + j * 8 + q * 2;
            float s0 = __ldg(&scale[col]);
            float s1 = __ldg(&scale[col + 1]);
            int r0 = bm + wm + mi * 16 + g;
            float2 v0 = make_float2(acc[mi][j][0] * s0, acc[mi][j][1] * s1);
            float2 v1 = make_float2(acc[mi][j][2] * s0, acc[mi][j][3] * s1);
            *(float2*)&C[(size_t)r0 * N + col] = v0;
            *(float2*)&C[(size_t)(r0 + 8) * N + col] = v1;
        }
    }
}

// ---------------- fused RMSNorm + RoPE + head transpose -> bf16 hi/lo -------
__global__ void norm_rope(const float* __restrict__ qnw, const float* __restrict__ knw,
                          const float* __restrict__ cosc, const float* __restrict__ sinc) {
    const int m = blockIdx.x;
    const int role = blockIdx.y;
    const int d = threadIdx.x;
    const int b = m / S_;
    const int s = m % S_;

    if (role >= 24) {                 // V: pure split + transpose
        int h = role - 24;
        float v = g_vproj[(size_t)m * NKV_ + h * HD_ + d];
        size_t o = ((size_t)(b * KVH_ + h) * S_ + s) * HD_ + d;
        __nv_bfloat16 hv = __float2bfloat16(v);
        g_Vhi[o] = hv;
        g_Vlo[o] = __float2bfloat16(v - __bfloat162float(hv));
        return;
    }

    const float* src;
    const float* nw;
    __nv_bfloat16 *dh, *dl;
    size_t o;
    if (role < 16) {                  // Q
        int h = role;
        src = &g_qproj[(size_t)m * NQ_ + h * HD_];
        nw = qnw;
        o = ((size_t)(b * H_ + h) * S_ + s) * HD_ + d;
        dh = g_Qhi; dl = g_Qlo;
    } else {                          // K
        int h = role - 16;
        src = &g_kproj[(size_t)m * NKV_ + h * HD_];
        nw = knw;
        o = ((size_t)(b * KVH_ + h) * S_ + s) * HD_ + d;
        dh = g_Khi; dl = g_Klo;
    }

    float val = src[d];
    float ss = val * val;
    #pragma unroll
    for (int of = 16; of > 0; of >>= 1) ss += __shfl_xor_sync(0xffffffffu, ss, of);
    __shared__ float wred[4];
    if ((d & 31) == 0) wred[d >> 5] = ss;
    __syncthreads();
    float tot = wred[0] + wred[1] + wred[2] + wred[3];
    float rms = rsqrtf(tot * (1.0f / HD_) + EPS_);

    int dp = (d < 64) ? d + 64 : d - 64;
    float sgn = (d < 64) ? -1.0f : 1.0f;
    float xn = val * rms * nw[d];
    float xp = src[dp] * rms * nw[dp];
    float c = cosc[(size_t)s * HD_ + d];
    float sn = sinc[(size_t)s * HD_ + d];
    float v = xn * c + sgn * xp * sn;
    __nv_bfloat16 hv = __float2bfloat16(v);
    dh[o] = hv;
    dl[o] = __float2bfloat16(v - __bfloat162float(hv));
}

// ---------------- tensor-core flash attention (bf16 hi/lo, causal, GQA) -----
#define BQA 128
#define BKVA 64
#define AQ_BYTES   32768        // 128 rows x 256B (per hi/lo)
#define AKV_STAGE  65536        // Khi,Klo,Vhi,Vlo each 16KB
#define ASMEM (2 * AQ_BYTES + 2 * AKV_STAGE)   // 192KB

__device__ __forceinline__ void a_load_kv(uint32_t kvbase, int buf, int kt, int nkv,
                                          size_t kvoff, int tid) {
    if (kt < nkv) {
        int k0 = kt * BKVA;
        uint32_t st = kvbase + buf * AKV_STAGE;
        #pragma unroll
        for (int t = 0; t < 4; t++) {
            int idx = tid + t * 256;          // 0..1023
            int row = idx >> 4;               // 0..63
            int ch = idx & 15;
            uint32_t off = sw256((uint32_t)(row * 256 + ch * 16));
            size_t gi = kvoff + (size_t)(k0 + row) * HD_ + ch * 8;
            cp16(st + off,         g_Khi + gi);
            cp16(st + 16384 + off, g_Klo + gi);
            cp16(st + 32768 + off, g_Vhi + gi);
            cp16(st + 49152 + off, g_Vlo + gi);
        }
    }
    CP_COMMIT();
}

__global__ __launch_bounds__(256, 1)
void attn_mma() {
    extern __shared__ char smraw[];
    uint32_t sb = smem_u32(smraw);
    const int tid = threadIdx.x;
    const int wid = tid >> 5;
    const int L = tid & 31;
    const int g = L >> 2;
    const int qd = L & 3;

    const int qt = (int)gridDim.x - 1 - (int)blockIdx.x;   // heavy tiles first
    const int bh = blockIdx.y;
    const int b = bh >> 4;
    const int h = bh & 15;
    const int kvh = h >> 1;
    const int q0 = qt * BQA;
    const int nkv = 2 * qt + 2;
    const int wm = wid * 16;

    const uint32_t Qh_s = sb;
    const uint32_t Ql_s = sb + AQ_BYTES;
    const uint32_t kvbase = sb + 2 * AQ_BYTES;

    const __nv_bfloat16* Qhg = g_Qhi + ((size_t)bh * S_ + q0) * HD_;
    const __nv_bfloat16* Qlg = g_Qlo + ((size_t)bh * S_ + q0) * HD_;
    const size_t kvoff = (size_t)(b * KVH_ + kvh) * S_ * HD_;

    // group0: Q + KV stage0
    #pragma unroll
    for (int t = 0; t < 8; t++) {
        int idx = tid + t * 256;          // 0..2047
        int row = idx >> 4;               // 0..127
        int ch = idx & 15;
        uint32_t off = sw256((uint32_t)(row * 256 + ch * 16));
        size_t gi = (size_t)row * HD_ + ch * 8;
        cp16(Qh_s + off, Qhg + gi);
        cp16(Ql_s + off, Qlg + gi);
    }
    a_load_kv(kvbase, 0, 0, nkv, kvoff, tid);
    // group1: stage1
    a_load_kv(kvbase, 1, 1, nkv, kvoff, tid);

    float m0 = -1e30f, m1 = -1e30f, l0 = 0.0f, l1 = 0.0f;
    float oa[16][4] = {};
    const float sc = 0.08838834764831845f;   // 1/sqrt(128)

    for (int kt = 0; kt < nkv; kt++) {
        CP_WAIT(1);
        __syncthreads();
        const int k0 = kt * BKVA;
        const int buf = kt & 1;
        if (k0 <= q0 + wm + 15) {
            uint32_t st = kvbase + buf * AKV_STAGE;
            uint32_t Kh = st, Kl = st + 16384, Vh = st + 32768, Vl = st + 49152;

            // ---- S = (Qhi+Qlo)(Khi+Klo)^T (3 passes) ----
            float sa[8][4] = {};
            const uint32_t a_part = (uint32_t)((L & 15) * 256 + ((L >> 4) << 4));
            const uint32_t b_row  = (uint32_t)((L & 7) + ((L >> 4) << 3));
            const uint32_t b_kb   = (uint32_t)(((L >> 3) & 1) * 16);
            #pragma unroll
            for (int k16 = 0; k16 < 8; k16++) {
                uint32_t qh[4], ql[4];
                uint32_t aoff = sw256((uint32_t)(wm * 256 + k16 * 32) + a_part);
                ldm4(qh, Qh_s + aoff);
                ldm4(ql, Ql_s + aoff);
                #pragma unroll
                for (int n16 = 0; n16 < 4; n16++) {
                    uint32_t boff = sw256((uint32_t)((n16 * 16 + b_row) * 256 + k16 * 32 + b_kb));
                    uint32_t kh4[4], kl4[4];
                    ldm4(kh4, Kh + boff);
                    ldm4(kl4, Kl + boff);
                    mma16816(sa[n16 * 2],     qh, &kh4[0]);
                    mma16816(sa[n16 * 2 + 1], qh, &kh4[2]);
                    mma16816(sa[n16 * 2],     ql, &kh4[0]);
                    mma16816(sa[n16 * 2 + 1], ql, &kh4[2]);
                    mma16816(sa[n16 * 2],     qh, &kl4[0]);
                    mma16816(sa[n16 * 2 + 1], qh, &kl4[2]);
                }
            }

            // ---- scale + causal mask ----
            const int r0 = q0 + wm + g;
            const int r1 = r0 + 8;
            const bool needmask = (k0 + 63 > q0 + wm);
            #pragma unroll
            for (int t = 0; t < 8; t++) {
                #pragma unroll
                for (int c = 0; c < 4; c++) {
                    float v = sa[t][c] * sc;
                    if (needmask) {
                        int col = k0 + t * 8 + 2 * qd + (c & 1);
                        int row = (c < 2) ? r0 : r1;
                        if (col > row) v = -1e30f;
                    }
                    sa[t][c] = v;
                }
            }

            // ---- online softmax (rows g, g+8; quad reduction) ----
            float mx0 = -1e30f, mx1 = -1e30f;
            #pragma unroll
            for (int t = 0; t < 8; t++) {
                mx0 = fmaxf(mx0, fmaxf(sa[t][0], sa[t][1]));
                mx1 = fmaxf(mx1, fmaxf(sa[t][2], sa[t][3]));
            }
            mx0 = fmaxf(mx0, __shfl_xor_sync(0xffffffffu, mx0, 1));
            mx0 = fmaxf(mx0, __shfl_xor_sync(0xffffffffu, mx0, 2));
            mx1 = fmaxf(mx1, __shfl_xor_sync(0xffffffffu, mx1, 1));
            mx1 = fmaxf(mx1, __shfl_xor_sync(0xffffffffu, mx1, 2));
            float nm0 = fmaxf(m0, mx0), nm1 = fmaxf(m1, mx1);
            float al0 = __expf(m0 - nm0), al1 = __expf(m1 - nm1);
            m0 = nm0; m1 = nm1;
            float rs0 = 0.0f, rs1 = 0.0f;
            #pragma unroll
            for (int t = 0; t < 8; t++) {
                float p0 = __expf(sa[t][0] - m0);
                float p1 = __expf(sa[t][1] - m0);
                float p2 = __expf(sa[t][2] - m1);
                float p3 = __expf(sa[t][3] - m1);
                sa[t][0] = p0; sa[t][1] = p1; sa[t][2] = p2; sa[t][3] = p3;
                rs0 += p0 + p1; rs1 += p2 + p3;
            }
            rs0 += __shfl_xor_sync(0xffffffffu, rs0, 1);
            rs0 += __shfl_xor_sync(0xffffffffu, rs0, 2);
            rs1 += __shfl_xor_sync(0xffffffffu, rs1, 1);
            rs1 += __shfl_xor_sync(0xffffffffu, rs1, 2);
            l0 = l0 * al0 + rs0;
            l1 = l1 * al1 + rs1;
            #pragma unroll
            for (int nt = 0; nt < 16; nt++) {
                oa[nt][0] *= al0; oa[nt][1] *= al0;
                oa[nt][2] *= al1; oa[nt][3] *= al1;
            }

            // ---- O += (Phi+Plo) (Vhi+Vlo) (3 passes), P from registers ----
            const uint32_t v_row = (uint32_t)((L & 7) + ((L >> 3) & 1) * 8);
            const uint32_t v_cb  = (uint32_t)((L >> 4) << 4);
            #pragma unroll
            for (int kk = 0; kk < 4; kk++) {
                const int t0 = 2 * kk, t1 = t0 + 1;
                uint32_t ph[4], pl[4];
                split2(sa[t0][0], sa[t0][1], ph[0], pl[0]);
                split2(sa[t0][2], sa[t0][3], ph[1], pl[1]);
                split2(sa[t1][0], sa[t1][1], ph[2], pl[2]);
                split2(sa[t1][2], sa[t1][3], ph[3], pl[3]);
                #pragma unroll
                for (int n16 = 0; n16 < 8; n16++) {
                    uint32_t voff = sw256((uint32_t)((kk * 16 + v_row) * 256 + n16 * 32) + v_cb);
                    uint32_t vh4[4], vl4[4];
                    ldm4t(vh4, Vh + voff);
                    ldm4t(vl4, Vl + voff);
                    mma16816(oa[n16 * 2],     ph, &vh4[0]);
                    mma16816(oa[n16 * 2 + 1], ph, &vh4[2]);
                    mma16816(oa[n16 * 2],     pl, &vh4[0]);
                    mma16816(oa[n16 * 2 + 1], pl, &vh4[2]);
                    mma16816(oa[n16 * 2],     ph, &vl4[0]);
                    mma16816(oa[n16 * 2 + 1], ph, &vl4[2]);
                }
            }
        }
        __syncthreads();
        a_load_kv(kvbase, buf, kt + 2, nkv, kvoff, tid);
    }

    // ---- epilogue: O/l -> bf16 hi/lo in [m, H*HD] ----
    float inv0 = 1.0f / l0, inv1 = 1.0f / l1;
    const int r0 = q0 + wm + g;
    const int r1 = r0 + 8;
    size_t base0 = ((size_t)(b * S_) + r0) * NQ_ + h * HD_;
    size_t base1 = ((size_t)(b * S_) + r1) * NQ_ + h * HD_;
    #pragma unroll
    for (int nt = 0; nt < 16; nt++) {
        int c = nt * 8 + 2 * qd;
        uint32_t hi, lo;
        split2(oa[nt][0] * inv0, oa[nt][1] * inv0, hi, lo);
        *(uint32_t*)&g_ahi[base0 + c] = hi;
        *(uint32_t*)&g_alo[base0 + c] = lo;
        split2(oa[nt][2] * inv1, oa[nt][3] * inv1, hi, lo);
        *(uint32_t*)&g_ahi[base1 + c] = hi;
        *(uint32_t*)&g_alo[base1 + c] = lo;
    }
}

// ---------------- launch ----------------
extern "C" void kernel_launch(void* const* d_in, const int* in_sizes, int n_in,
                              void* d_out, int out_size) {
    const float* x    = (const float*)d_in[0];
    const int*   wq   = (const int*)  d_in[1];
    const float* wqs  = (const float*)d_in[2];
    const int*   wk   = (const int*)  d_in[3];
    const float* wks  = (const float*)d_in[4];
    const int*   wv   = (const int*)  d_in[5];
    const float* wvs  = (const float*)d_in[6];
    const int*   wo   = (const int*)  d_in[7];
    const float* wos  = (const float*)d_in[8];
    const float* qnw  = (const float*)d_in[9];
    const float* knw  = (const float*)d_in[10];
    const float* cosc = (const float*)d_in[11];
    const float* sinc = (const float*)d_in[12];
    float* out = (float*)d_out;

    float *qp, *kp, *vp;
    __nv_bfloat16 *xhi, *xlo, *ahi, *alo, *wqb, *wkb, *wvb, *wob;
    cudaGetSymbolAddress((void**)&qp,  g_qproj);
    cudaGetSymbolAddress((void**)&kp,  g_kproj);
    cudaGetSymbolAddress((void**)&vp,  g_vproj);
    cudaGetSymbolAddress((void**)&xhi, g_xhi);
    cudaGetSymbolAddress((void**)&xlo, g_xlo);
    cudaGetSymbolAddress((void**)&ahi, g_ahi);
    cudaGetSymbolAddress((void**)&alo, g_alo);
    cudaGetSymbolAddress((void**)&wqb, g_wqb);
    cudaGetSymbolAddress((void**)&wkb, g_wkb);
    cudaGetSymbolAddress((void**)&wvb, g_wvb);
    cudaGetSymbolAddress((void**)&wob, g_wob);

    split_x_kernel<<<(M_ * D_ / 4) / 256, 256>>>(x, xhi, xlo);
    cvt_w_kernel<<<(NQ_ * D_ / 4) / 256, 256>>>(wq, wqb);
    cvt_w_kernel<<<(NKV_ * D_ / 4) / 256, 256>>>(wk, wkb);
    cvt_w_kernel<<<(NKV_ * D_ / 4) / 256, 256>>>(wv, wvb);
    cvt_w_kernel<<<(NQ_ * D_ / 4) / 256, 256>>>(wo, wob);

    cudaFuncSetAttribute(gemm_mma, cudaFuncAttributeMaxDynamicSharedMemorySize, GSMEM_DYN);

    gemm_mma<<<dim3(NQ_ / 128,  M_ / 128), 256, GSMEM_DYN>>>(xhi, xlo, wqb, wqs, qp, NQ_);
    gemm_mma<<<dim3(NKV_ / 128, M_ / 128), 256, GSMEM_DYN>>>(xhi, xlo, wkb, wks, kp, NKV_);
    gemm_mma<<<dim3(NKV_ / 128, M_ / 128), 256, GSMEM_DYN>>>(xhi, xlo, wvb, wvs, vp, NKV_);

    norm_rope<<<dim3(M_, H_ + 2 * KVH_), 128>>>(qnw, knw, cosc, sinc);

    cudaFuncSetAttribute(attn_mma, cudaFuncAttributeMaxDynamicSharedMemorySize, ASMEM);
    attn_mma<<<dim3(S_ / BQA, B_ * H_), 256, ASMEM>>>();

    gemm_mma<<<dim3(D_ / 128, M_ / 128), 256, GSMEM_DYN>>>(ahi, alo, wob, wos, out, D_);
}